// round 17
// baseline (speedup 1.0000x reference)
#include <cuda_runtime.h>

// ---------------------------------------------------------------------------
// RadarSecondStageGenerator, fused, persistent (R16 base, 97.0us).
// R17: 3 CTAs/SM — 6-channel chunks (smem 69.8KB), launch_bounds(256,3),
// 8-byte cp.async loader (pair-aligned, validity clean at tile edges).
// Compute loops identical to R16 -> bit-identical results.
// ---------------------------------------------------------------------------

#define THREADS 256
#define TX 32
#define TY 16
#define NUM_CTAS 456          // 3 per SM on GB300 (152 SMs)
#define NTILES 1024           // 4 x 8 x 32

// shared memory layout (in floats)
#define CHUNK_FLOATS (6*20*36)              // 4320 (6ch, 20x36 halo-2 tile)
#define IN0_OFF    0
#define IN1_OFF    (IN0_OFF + CHUNK_FLOATS)
#define X_S_OFF    (IN1_OFF + CHUNK_FLOATS) // [8][18][36] x tile + halo1
#define X_S_SIZE   (8*18*36)
#define WCIN_OFF   (X_S_OFF + X_S_SIZE)     // [ci=24][k=9][co=8]
#define WI2H_OFF   (WCIN_OFF + 1728)        // [ci=8][k=9][o=24]
#define WOUT_OFF   (WI2H_OFF + 1728)        // [t=12][c=8]
#define BCIN_OFF   (WOUT_OFF + 96)
#define BI2H_OFF   (BCIN_OFF + 8)
#define BRET_OFF   (BI2H_OFF + 24)
#define BOUT_OFF   (BRET_OFF + 24)
#define TT_OFF     (BOUT_OFF + 12)          // next-ticket broadcast slot
#define SMEM_FLOATS (TT_OFF + 1)
#define SMEM_BYTES (SMEM_FLOATS * 4)

typedef unsigned long long u64;

__device__ unsigned g_ticket;

__device__ __forceinline__ float sigmoidf_(float x) {
    return __fdividef(1.0f, 1.0f + __expf(-x));
}
__device__ __forceinline__ u64 pk2(float lo, float hi) {
    u64 r; asm("mov.b64 %0, {%1, %2};" : "=l"(r) : "f"(lo), "f"(hi)); return r;
}
__device__ __forceinline__ u64 ffma2(u64 a, u64 b, u64 c) {
    u64 d; asm("fma.rn.f32x2 %0, %1, %2, %3;" : "=l"(d) : "l"(a), "l"(b), "l"(c)); return d;
}
__device__ __forceinline__ float2 upk2(u64 v) {
    float2 f; asm("mov.b64 {%0, %1}, %2;" : "=f"(f.x), "=f"(f.y) : "l"(v)); return f;
}

// 8-byte async chunk loader. CHUNK selects channels [CHUNK*6, CHUNK*6+6) at
// compile time. Thread map: lpx = pair column (0..17), lt rows {lt, lt+14}.
// Pairs are 8B-aligned in gmem (gx even) and never straddle the image edge
// (tile x-origins are multiples of 32, halo is +-2).
template<int CHUNK>
__device__ __forceinline__ void issue_chunk2(const float* __restrict__ radar,
                                             const float* __restrict__ pred,
                                             int b, int ty0, int gx, bool vx,
                                             int lt, unsigned dstb)
{
    if (lt < 14) {
        const float* bases[6];
        #pragma unroll
        for (int cc = 0; cc < 6; cc++) {
            int ch = CHUNK * 6 + cc;
            bases[cc] = (ch < 12) ? radar + ((b * 12 + ch) << 14)
                                  : pred  + ((b * 12 + ch - 12) << 14);
        }
        #pragma unroll
        for (int k = 0; k < 2; k++) {
            const int yy = lt + 14 * k;
            if (yy < 20) {
                const int gy = ty0 + yy - 2;
                const bool v = vx && ((unsigned)gy < 128u);
                const int off = v ? ((gy << 7) + gx) : 0;
                const int sz = v ? 8 : 0;
                const unsigned dst = dstb + (unsigned)(yy * 144);
                #pragma unroll
                for (int cc = 0; cc < 6; cc++) {
                    asm volatile("cp.async.ca.shared.global [%0], [%1], 8, %2;"
                                 :: "r"(dst + (unsigned)(cc * 2880)),
                                    "l"(bases[cc] + off), "r"(sz));
                }
            }
        }
    }
}

__global__ void reset_ticket_kernel() { g_ticket = 0u; }

__global__ void __launch_bounds__(THREADS, 3)
radar2nd_persist_kernel(const float* __restrict__ radar,
                        const float* __restrict__ pred,
                        const float* __restrict__ w_cin,
                        const float* __restrict__ b_cin,
                        const float* __restrict__ w_i2h,
                        const float* __restrict__ b_i2h,
                        const float* __restrict__ b_ret,
                        const float* __restrict__ w_out,
                        const float* __restrict__ b_out,
                        float* __restrict__ out)
{
    extern __shared__ float sm[];
    float* x_s    = sm + X_S_OFF;
    float* wcin_s = sm + WCIN_OFF;
    float* wi2h_s = sm + WI2H_OFF;
    float* wout_s = sm + WOUT_OFF;
    float* bcin_s = sm + BCIN_OFF;
    float* bi2h_s = sm + BI2H_OFF;
    float* bret_s = sm + BRET_OFF;
    float* bout_s = sm + BOUT_OFF;
    unsigned* tt_s = (unsigned*)(sm + TT_OFF);

    const int tid = threadIdx.x;
    const unsigned smem_base = (unsigned)__cvta_generic_to_shared(sm);

    // loader map: 18 pair-columns x 14 row-threads (computed once)
    const int lpx = tid % 18;                 // pair column 0..17
    const int lt  = tid / 18;                 // 0..14; lt==14 -> loader-idle
    const unsigned dst_col = smem_base + (unsigned)(lpx * 8);
    const int gxr = lpx * 2 - 2;              // gx relative to tx0 (even)

    // ---------------- stage weights once per CTA --------------------------
    for (int i = tid; i < 1728; i += THREADS) {
        int co = i & 7;
        int r  = i >> 3;
        int ci = r / 9;
        int k  = r - ci * 9;
        wcin_s[i] = w_cin[(co * 24 + ci) * 9 + k];
    }
    for (int i = tid; i < 1728; i += THREADS) {
        int o  = i % 24;
        int r  = i / 24;
        int ci = r / 9;
        int k  = r - ci * 9;
        wi2h_s[i] = w_i2h[(o * 8 + ci) * 9 + k];
    }
    if (tid < 96) wout_s[tid] = w_out[tid];
    if (tid < 8)  bcin_s[tid] = b_cin[tid];
    if (tid < 24) bi2h_s[tid] = b_i2h[tid];
    if (tid < 24) bret_s[tid] = b_ret[tid];
    if (tid < 12) bout_s[tid] = b_out[tid];

    // first ticket
    if (tid == 0) tt_s[0] = atomicAdd(&g_ticket, 1u);
    __syncthreads();   // weights + biases + first ticket visible
    int tt = (int)tt_s[0];

    // prologue: async-load chunk 0 of first tile into buf 0
    if (tt < NTILES) {
        int b0   = tt >> 5;
        int ty00 = ((tt >> 2) & 7) * TY;
        int tx00 = (tt & 3) * TX;
        int gx0  = tx00 + gxr;
        issue_chunk2<0>(radar, pred, b0, ty00, gx0, (unsigned)gx0 < 128u,
                        lt, dst_col + IN0_OFF * 4);
    }
    asm volatile("cp.async.commit_group;");

    int cur = 0;       // ping-pong buffer holding the next chunk to consume

    // phase-2 thread map: 3-px strips, 12 strips/row x 18 rows = 216 threads
    const int p2row = tid / 12;
    const int p2xs  = (tid - p2row * 12) * 3;
    // phase-3 thread map: 2-px strips, 16 strips/row x 16 rows = 256 threads
    const int p3row = tid >> 4;
    const int p3xs  = (tid & 15) * 2;

    #pragma unroll 1
    while (tt < NTILES) {
        const int b   = tt >> 5;
        const int ty0 = ((tt >> 2) & 7) * TY;
        const int tx0 = (tt & 3) * TX;

        // fetch next ticket early (visible by the c==3 sync below)
        if (tid == 0) tt_s[0] = atomicAdd(&g_ticket, 1u);

        u64 acc2[4][3];                     // [co_pair][px]
        #pragma unroll
        for (int cp = 0; cp < 4; cp++) {
            u64 bv = pk2(bcin_s[2 * cp], bcin_s[2 * cp + 1]);
            #pragma unroll
            for (int px = 0; px < 3; px++) acc2[cp][px] = bv;
        }

        int ntt = NTILES;                   // next tile (read at c==3)

        // ---------- chunked conv3x3(24->8), cp.async pipelined ------------
        #pragma unroll 1
        for (int c = 0; c < 4; c++) {
            asm volatile("cp.async.wait_group 0;");
            __syncthreads();                // chunk c data visible; buf cur^1 free

            // issue next chunk (c+1 of this tile, or chunk 0 of next tile)
            {
                unsigned dstb = dst_col +
                    (unsigned)((cur ? IN0_OFF : IN1_OFF) * 4);
                int gx = tx0 + gxr;
                bool vx = (unsigned)gx < 128u;
                if (c == 0) {
                    issue_chunk2<1>(radar, pred, b, ty0, gx, vx, lt, dstb);
                } else if (c == 1) {
                    issue_chunk2<2>(radar, pred, b, ty0, gx, vx, lt, dstb);
                } else if (c == 2) {
                    issue_chunk2<3>(radar, pred, b, ty0, gx, vx, lt, dstb);
                } else {
                    ntt = (int)tt_s[0];     // made visible by this chunk's sync
                    if (ntt < NTILES) {
                        int nb   = ntt >> 5;
                        int nty0 = ((ntt >> 2) & 7) * TY;
                        int ntx0 = (ntt & 3) * TX;
                        int ngx  = ntx0 + gxr;
                        issue_chunk2<0>(radar, pred, nb, nty0, ngx,
                                        (unsigned)ngx < 128u, lt, dstb);
                    }
                }
            }
            asm volatile("cp.async.commit_group;");

            // accumulate this chunk (6 channels)
            if (tid < 216) {
                const float* in_s = sm + (cur ? IN1_OFF : IN0_OFF);
                #pragma unroll 1
                for (int cc = 0; cc < 6; cc++) {
                    const int ci = c * 6 + cc;
                    #pragma unroll
                    for (int dy = 0; dy < 3; dy++) {
                        const float* ap = &in_s[(cc * 20 + p2row + dy) * 36 + p2xs];
                        u64 ad[5];
                        #pragma unroll
                        for (int q = 0; q < 5; q++) { float a = ap[q]; ad[q] = pk2(a, a); }
                        #pragma unroll
                        for (int dx = 0; dx < 3; dx++) {
                            const u64* wp2 = (const u64*)&wcin_s[((ci * 3 + dy) * 3 + dx) * 8];
                            ulonglong2 wA = *(const ulonglong2*)(wp2);
                            ulonglong2 wB = *(const ulonglong2*)(wp2 + 2);
                            u64 wv[4] = {wA.x, wA.y, wB.x, wB.y};
                            #pragma unroll
                            for (int cp = 0; cp < 4; cp++) {
                                #pragma unroll
                                for (int px = 0; px < 3; px++)
                                    acc2[cp][px] = ffma2(ad[dx + px], wv[cp], acc2[cp][px]);
                            }
                        }
                    }
                }
            }
            cur ^= 1;
        }

        // store x; outside the global image x is ZERO (2nd conv's padding)
        if (tid < 216) {
            const int gyr2 = ty0 + p2row - 1;
            const bool rin = (unsigned)gyr2 < 128u;
            #pragma unroll
            for (int px = 0; px < 3; px++) {
                int cxl = p2xs + px;
                if (cxl < 34) {
                    const int gxc = tx0 + cxl - 1;
                    const bool inb = rin && ((unsigned)gxc < 128u);
                    #pragma unroll
                    for (int cp = 0; cp < 4; cp++) {
                        float2 v = upk2(acc2[cp][px]);
                        x_s[((2 * cp + 0) * 18 + p2row) * 36 + cxl] = inb ? v.x : 0.0f;
                        x_s[((2 * cp + 1) * 18 + p2row) * 36 + cxl] = inb ? v.y : 0.0f;
                    }
                }
            }
        }
        __syncthreads();

        // ---------- phase 3: i2h conv3x3(8->24) + gates + conv1x1 ---------
        {
            u64 acc3[12][2];                // [o_pair][px]
            #pragma unroll
            for (int op = 0; op < 12; op++) {
                u64 bv = pk2(bi2h_s[2 * op], bi2h_s[2 * op + 1]);
                acc3[op][0] = bv; acc3[op][1] = bv;
            }

            #pragma unroll 1
            for (int ci = 0; ci < 8; ci++) {
                #pragma unroll
                for (int dy = 0; dy < 3; dy++) {
                    const float* ap = &x_s[(ci * 18 + p3row + dy) * 36 + p3xs];
                    float2 a01 = *(const float2*)ap;
                    float2 a23 = *(const float2*)(ap + 2);
                    u64 ad[4];
                    ad[0] = pk2(a01.x, a01.x); ad[1] = pk2(a01.y, a01.y);
                    ad[2] = pk2(a23.x, a23.x); ad[3] = pk2(a23.y, a23.y);
                    #pragma unroll
                    for (int dx = 0; dx < 3; dx++) {
                        const u64* wp2 = (const u64*)&wi2h_s[(ci * 9 + dy * 3 + dx) * 24];
                        #pragma unroll
                        for (int q = 0; q < 6; q++) {
                            ulonglong2 w2 = *(const ulonglong2*)(wp2 + q * 2);
                            #pragma unroll
                            for (int px = 0; px < 2; px++) {
                                acc3[2 * q + 0][px] = ffma2(ad[dx + px], w2.x, acc3[2 * q + 0][px]);
                                acc3[2 * q + 1][px] = ffma2(ad[dx + px], w2.y, acc3[2 * q + 1][px]);
                            }
                        }
                    }
                }
            }

            // gates (h2h from h0==0 is just b_ret broadcast)
            float h[8][2];
            #pragma unroll
            for (int cp = 0; cp < 4; cp++) {
                float br0 = bret_s[2 * cp],      br1 = bret_s[2 * cp + 1];
                float bu0 = bret_s[8 + 2 * cp],  bu1 = bret_s[8 + 2 * cp + 1];
                float bm0 = bret_s[16 + 2 * cp], bm1 = bret_s[16 + 2 * cp + 1];
                #pragma unroll
                for (int px = 0; px < 2; px++) {
                    float2 ir = upk2(acc3[cp][px]);
                    float2 iu = upk2(acc3[4 + cp][px]);
                    float2 im = upk2(acc3[8 + cp][px]);
                    float rg0 = sigmoidf_(ir.x + br0);
                    float rg1 = sigmoidf_(ir.y + br1);
                    float ug0 = sigmoidf_(iu.x + bu0);
                    float ug1 = sigmoidf_(iu.y + bu1);
                    float m0 = fmaf(rg0, bm0, im.x);
                    float m1 = fmaf(rg1, bm1, im.y);
                    m0 = (m0 >= 0.0f) ? m0 : 0.2f * m0;
                    m1 = (m1 >= 0.0f) ? m1 : 0.2f * m1;
                    h[2 * cp + 0][px] = (1.0f - ug0) * m0;
                    h[2 * cp + 1][px] = (1.0f - ug1) * m1;
                }
            }

            // conv1x1 (8 -> 12) + store
            const int gy  = ty0 + p3row;
            const int gx0 = tx0 + p3xs;
            float* op_ = out + ((b * 12) << 14) + (gy << 7) + gx0;
            u64 hp[8];
            #pragma unroll
            for (int cch = 0; cch < 8; cch++) hp[cch] = pk2(h[cch][0], h[cch][1]);
            #pragma unroll
            for (int t = 0; t < 12; t++) {
                u64 o01 = pk2(bout_s[t], bout_s[t]);
                #pragma unroll
                for (int cch = 0; cch < 8; cch++) {
                    float w = wout_s[t * 8 + cch];
                    o01 = ffma2(hp[cch], pk2(w, w), o01);
                }
                float2 a = upk2(o01);
                *(float2*)(op_ + (t << 14)) = a;
            }
        }

        tt = ntt;
        // next iteration's chunk-top wait+sync protects x_s and buffers
    }
}

extern "C" void kernel_launch(void* const* d_in, const int* in_sizes, int n_in,
                              void* d_out, int out_size)
{
    const float* radar = (const float*)d_in[0];   // (32,12,1,128,128)
    const float* pred  = (const float*)d_in[1];   // (32,12,1,128,128)
    const float* w_cin = (const float*)d_in[2];   // (8,24,3,3)
    const float* b_cin = (const float*)d_in[3];   // (8,)
    const float* w_i2h = (const float*)d_in[4];   // (24,8,3,3)
    const float* b_i2h = (const float*)d_in[5];   // (24,)
    // d_in[6..12]: flow-path params + w_ret -> dead code with h0 == 0
    const float* b_ret = (const float*)d_in[13];  // (24,)
    const float* w_out = (const float*)d_in[14];  // (12,8,1,1)
    const float* b_out = (const float*)d_in[15];  // (12,)
    float* out = (float*)d_out;                   // (32,12,1,128,128)

    cudaFuncSetAttribute(radar2nd_persist_kernel,
                         cudaFuncAttributeMaxDynamicSharedMemorySize, SMEM_BYTES);

    reset_ticket_kernel<<<1, 1>>>();
    radar2nd_persist_kernel<<<NUM_CTAS, THREADS, SMEM_BYTES>>>(
        radar, pred, w_cin, b_cin, w_i2h, b_i2h, b_ret, w_out, b_out, out);
}